// round 9
// baseline (speedup 1.0000x reference)
#include <cuda_runtime.h>
#include <cuda_fp16.h>
#include <cstdint>

#define B_  16
#define N_  2048
#define D_  128
#define BM  128
#define BN  64
#define NT  256
#define NTP 256
#define NTILES (N_/BN)        // 32

#define KRS 144               // int8 K/Q smem row stride
#define KTS (64*KRS)          // 9216
#define VRS 272               // fp16 V smem row stride
#define VTS (64*VRS)          // 17408
#define SM_KH(st) ((st)*2*KTS)
#define SM_KL(st) ((st)*2*KTS + KTS)
#define SM_V(st)  (4*KTS + (st)*VTS)
#define SM_RK     (4*KTS + 2*VTS)          // 71680: rk table 2048 floats
#define SMEM_TOTAL (SM_RK + 8192)          // 79872

// -------- static device scratch --------
__device__ __align__(256) char   g_Qh8[B_*N_*D_];
__device__ __align__(256) char   g_Ql8[B_*N_*D_];
__device__ __align__(256) char   g_Kh8[B_*N_*D_];
__device__ __align__(256) char   g_Kl8[B_*N_*D_];
__device__ __align__(256) __half g_Vh[B_*N_*D_];
__device__ __align__(256) float  g_rq[B_*N_];
__device__ __align__(256) float  g_rk[B_*N_];

// -------- PTX helpers --------
__device__ __forceinline__ uint32_t smem_u32(const void* p) {
    uint32_t a;
    asm("{ .reg .u64 t; cvta.to.shared.u64 t, %1; cvt.u32.u64 %0, t; }" : "=r"(a) : "l"(p));
    return a;
}
__device__ __forceinline__ void cpa16(uint32_t dst, const void* src) {
    asm volatile("cp.async.cg.shared.global [%0], [%1], 16;" :: "r"(dst), "l"(src) : "memory");
}
#define CP_COMMIT() asm volatile("cp.async.commit_group;" ::: "memory")
#define CP_WAIT(n)  asm volatile("cp.async.wait_group %0;" :: "n"(n) : "memory")

__device__ __forceinline__ void ldsm4(uint32_t* r, uint32_t a) {
    asm volatile("ldmatrix.sync.aligned.m8n8.x4.shared.b16 {%0,%1,%2,%3}, [%4];"
        : "=r"(r[0]), "=r"(r[1]), "=r"(r[2]), "=r"(r[3]) : "r"(a));
}
__device__ __forceinline__ void ldsm4t(uint32_t* r, uint32_t a) {
    asm volatile("ldmatrix.sync.aligned.m8n8.x4.trans.shared.b16 {%0,%1,%2,%3}, [%4];"
        : "=r"(r[0]), "=r"(r[1]), "=r"(r[2]), "=r"(r[3]) : "r"(a));
}
__device__ __forceinline__ void mma16816(float* c, const uint32_t* a, uint32_t b0, uint32_t b1) {
    asm volatile(
        "mma.sync.aligned.m16n8k16.row.col.f32.f16.f16.f32 "
        "{%0,%1,%2,%3}, {%4,%5,%6,%7}, {%8,%9}, {%0,%1,%2,%3};"
        : "+f"(c[0]), "+f"(c[1]), "+f"(c[2]), "+f"(c[3])
        : "r"(a[0]), "r"(a[1]), "r"(a[2]), "r"(a[3]), "r"(b0), "r"(b1));
}
// sole IMMA variant: s8 x s8 -> s32 (native fast path)
__device__ __forceinline__ void imma_ss(int* c, const uint32_t* a, uint32_t b0, uint32_t b1) {
    asm volatile(
        "mma.sync.aligned.m16n8k32.row.col.s32.s8.s8.s32 "
        "{%0,%1,%2,%3}, {%4,%5,%6,%7}, {%8,%9}, {%0,%1,%2,%3};"
        : "+r"(c[0]), "+r"(c[1]), "+r"(c[2]), "+r"(c[3])
        : "r"(a[0]), "r"(a[1]), "r"(a[2]), "r"(a[3]), "r"(b0), "r"(b1));
}

__device__ __forceinline__ uint32_t pack_h2(float a, float b) {
    __half2 h = __floats2half2_rn(a, b);
    return *(uint32_t*)&h;
}
__device__ __forceinline__ float ex2(float x) {
    float r;
    asm("ex2.approx.ftz.f32 %0, %1;" : "=f"(r) : "f"(x));
    return r;
}

// -------- prep: per-row int16 quantization, all-signed hi/lo split --------
__global__ void prep_qk_kernel(const float* __restrict__ Q, const float* __restrict__ K) {
    int gw = (blockIdx.x * blockDim.x + threadIdx.x) >> 5;   // global row 0..65535
    int lane = threadIdx.x & 31;
    bool isK = gw >= B_ * N_;
    int row = isK ? gw - B_ * N_ : gw;
    const float* src = (isK ? K : Q) + (size_t)row * D_;
    float4 v = ((const float4*)src)[lane];
    float am = fmaxf(fmaxf(fabsf(v.x), fabsf(v.y)), fmaxf(fabsf(v.z), fabsf(v.w)));
#pragma unroll
    for (int d = 16; d; d >>= 1) am = fmaxf(am, __shfl_xor_sync(0xffffffffu, am, d));
    float s = 32256.0f / am;
    int xi[4];
    xi[0] = __float2int_rn(v.x * s); xi[1] = __float2int_rn(v.y * s);
    xi[2] = __float2int_rn(v.z * s); xi[3] = __float2int_rn(v.w * s);
    uint32_t hw = 0, lw = 0;
#pragma unroll
    for (int e = 0; e < 4; e++) {
        int hi = (xi[e] + 128) >> 8;          // s8, |hi| <= 126
        int lo = xi[e] - (hi << 8);           // s8, in [-128, 128)
        hw |= (uint32_t)(hi & 255) << (8 * e);
        lw |= (uint32_t)(lo & 255) << (8 * e);
    }
    ((uint32_t*)(isK ? g_Kh8 : g_Qh8))[row * 32 + lane] = hw;
    ((uint32_t*)(isK ? g_Kl8 : g_Ql8))[row * 32 + lane] = lw;
    if (lane == 0) {
        if (isK) g_rk[row] = 1.0f / s;
        else     g_rq[row] = 1.44269504089f / s;   // fold log2e into q-side scale
    }
}

__global__ void prep_v_kernel(const float* __restrict__ V) {
    size_t i = (size_t)blockIdx.x * blockDim.x + threadIdx.x;
    float2 v = ((const float2*)V)[i];
    ((__half2*)g_Vh)[i] = __floats2half2_rn(v.x, v.y);
}

// -------- pipeline group loader --------
__device__ __forceinline__ void issue_group(uint32_t sb, size_t boff, int u, int tid) {
    const char* kh = g_Kh8 + boff + (size_t)u * BN * D_;
    const char* kl = g_Kl8 + boff + (size_t)u * BN * D_;
    uint32_t kdst = sb + SM_KH(u & 1);
#pragma unroll
    for (int i = 0; i < 2; i++) {
        int g = tid + i * NT;
        int row = g >> 3, c = g & 7;
        cpa16(kdst + row * KRS + c * 16, kh + row * 128 + c * 16);
        cpa16(kdst + KTS + row * KRS + c * 16, kl + row * 128 + c * 16);
    }
    const char* v = (const char*)(g_Vh) + 2 * (boff + (size_t)u * BN * D_);
    uint32_t vdst = sb + SM_V(u & 1);
#pragma unroll
    for (int i = 0; i < 4; i++) {
        int g = tid + i * NT;
        int row = g >> 4, c = g & 15;
        cpa16(vdst + row * VRS + c * 16, v + row * 256 + c * 16);
    }
}

// -------- main attention kernel --------
__global__ void __launch_bounds__(NT, 1)
attn_imma_kernel(float* __restrict__ O)
{
    extern __shared__ __align__(1024) char smem[];
    uint32_t sb = smem_u32(smem);
    const int tid  = threadIdx.x;
    const int warp = tid >> 5;
    const int lane = tid & 31;
    const int qt = blockIdx.x;
    const int b  = blockIdx.y;

    const int m0 = warp * 16;
    const uint32_t qrow = m0 + (lane & 7) + ((lane & 8) ? 8 : 0);
    const uint32_t krow = (lane & 7) + ((lane & 16) ? 8 : 0);
    const uint32_t kcol = (lane & 8) ? 16 : 0;
    const uint32_t vrow = (lane & 7) + ((lane & 8) ? 8 : 0);
    const uint32_t vcol = (lane & 16) ? 16 : 0;

    // ---- stage Q int8 through the K region (disjoint from rk table) ----
    {
        const char* qh8 = g_Qh8 + ((size_t)b * N_ + (size_t)qt * BM) * D_;
        const char* ql8 = g_Ql8 + ((size_t)b * N_ + (size_t)qt * BM) * D_;
#pragma unroll
        for (int i = 0; i < 4; i++) {
            int g = tid + i * NT;
            int row = g >> 3, c = g & 7;                     // 128 rows x 128B
            cpa16(sb + SM_KH(0) + row * KRS + c * 16, qh8 + row * 128 + c * 16);
            cpa16(sb + SM_KH(1) + row * KRS + c * 16, ql8 + row * 128 + c * 16);
        }
        const char* rkg = (const char*)(g_rk + (size_t)b * N_);
#pragma unroll
        for (int i = 0; i < 2; i++) {
            int g = tid + i * NT;
            cpa16(sb + SM_RK + g * 16, rkg + g * 16);
        }
        CP_COMMIT();
        CP_WAIT(0);
        __syncthreads();
    }

    uint32_t qfh[4][4], qfl[4][4];
    {
        uint32_t aq = sb + SM_KH(0) + qrow * KRS + ((lane & 16) ? 16 : 0);
#pragma unroll
        for (int k = 0; k < 4; k++) {
            ldsm4(qfh[k], aq + k * 32);
            ldsm4(qfl[k], aq + (uint32_t)SM_KH(1) + k * 32);
        }
    }
    const float* rqg = g_rq + (size_t)b * N_ + (size_t)qt * BM;
    const float rq0 = rqg[m0 + (lane >> 2)];
    const float rq1 = rqg[m0 + (lane >> 2) + 8];
    __syncthreads();        // Q frags hoisted; K region may now be recycled

    // ---- KV pipeline prologue ----
    const size_t boff = (size_t)b * N_ * D_;
    issue_group(sb, boff, 0, tid); CP_COMMIT();
    issue_group(sb, boff, 1, tid); CP_COMMIT();

    float o[16][4];
#pragma unroll
    for (int i = 0; i < 16; i++)
#pragma unroll
        for (int j = 0; j < 4; j++) o[i][j] = 0.f;
    float m0r = -INFINITY, m1r = -INFINITY, l0 = 0.f, l1 = 0.f;

    CP_WAIT(1);
    __syncthreads();

    for (int t = 0; t < NTILES; t++) {
        const uint32_t akh = sb + SM_KH(t & 1) + krow * KRS + kcol;
        const uint32_t akl = sb + SM_KL(t & 1) + krow * KRS + kcol;
        const uint32_t avh = sb + SM_V(t & 1) + vrow * VRS + vcol;

        float s[8][4];

        // ---- S-GEMM: stream over the 4 column-blocks p (register-lean) ----
#pragma unroll
        for (int p = 0; p < 4; p++) {
            int a1[8], a2[8];
#pragma unroll
            for (int i = 0; i < 8; i++) { a1[i] = 0; a2[i] = 0; }

            // phase A: Kh fragments -> hh (a1), ql*kh (a2)
#pragma unroll
            for (int k = 0; k < 4; k++) {
                uint32_t bb[4];
                ldsm4(bb, akh + p * (16 * KRS) + k * 32);
                imma_ss(a1 + 0, qfh[k], bb[0], bb[1]);
                imma_ss(a1 + 4, qfh[k], bb[2], bb[3]);
                imma_ss(a2 + 0, qfl[k], bb[0], bb[1]);
                imma_ss(a2 + 4, qfl[k], bb[2], bb[3]);
            }
            float hhf[8];
#pragma unroll
            for (int i = 0; i < 8; i++) { hhf[i] = (float)a1[i]; a1[i] = 0; }

            // phase B: Kl fragments -> qh*kl (a2), ql*kl (a1)
#pragma unroll
            for (int k = 0; k < 4; k++) {
                uint32_t bb[4];
                ldsm4(bb, akl + p * (16 * KRS) + k * 32);
                imma_ss(a2 + 0, qfh[k], bb[0], bb[1]);
                imma_ss(a2 + 4, qfh[k], bb[2], bb[3]);
                imma_ss(a1 + 0, qfl[k], bb[0], bb[1]);
                imma_ss(a1 + 4, qfl[k], bb[2], bb[3]);
            }

            // dequant: S = (2^16 hh + 2^8 mid + ll) * rq_i * rk_j  (log2 units)
#pragma unroll
            for (int h = 0; h < 2; h++) {
                int nt = 2 * p + h;
                float2 rk2 = *(const float2*)(smem + SM_RK +
                              ((t * 64) + p * 16 + h * 8 + 2 * (lane & 3)) * 4);
#pragma unroll
                for (int e = 0; e < 4; e++) {
                    float r = ((e < 2) ? rq0 : rq1) * ((e & 1) ? rk2.y : rk2.x);
                    float tmid = fmaf((float)a2[4 * h + e], 256.f, (float)a1[4 * h + e]);
                    s[nt][e] = fmaf(hhf[4 * h + e] * 65536.f, r, tmid * r);
                }
            }
        }

        // ---- online softmax (log2 domain, ex2) ----
        float mx0 = s[0][0], mx1 = s[0][2];
#pragma unroll
        for (int nt = 0; nt < 8; nt++) {
            mx0 = fmaxf(mx0, fmaxf(s[nt][0], s[nt][1]));
            mx1 = fmaxf(mx1, fmaxf(s[nt][2], s[nt][3]));
        }
        mx0 = fmaxf(mx0, __shfl_xor_sync(0xffffffffu, mx0, 1));
        mx0 = fmaxf(mx0, __shfl_xor_sync(0xffffffffu, mx0, 2));
        mx1 = fmaxf(mx1, __shfl_xor_sync(0xffffffffu, mx1, 1));
        mx1 = fmaxf(mx1, __shfl_xor_sync(0xffffffffu, mx1, 2));
        float mn0 = fmaxf(m0r, mx0), mn1 = fmaxf(m1r, mx1);
        float c0 = ex2(m0r - mn0), c1 = ex2(m1r - mn1);
        m0r = mn0; m1r = mn1;
        float a0 = 0.f, aa1 = 0.f;
#pragma unroll
        for (int nt = 0; nt < 8; nt++) {
            s[nt][0] = ex2(s[nt][0] - mn0); a0 += s[nt][0];
            s[nt][1] = ex2(s[nt][1] - mn0); a0 += s[nt][1];
            s[nt][2] = ex2(s[nt][2] - mn1); aa1 += s[nt][2];
            s[nt][3] = ex2(s[nt][3] - mn1); aa1 += s[nt][3];
        }
        l0 = l0 * c0 + a0;
        l1 = l1 * c1 + aa1;
#pragma unroll
        for (int nt = 0; nt < 16; nt++) {
            o[nt][0] *= c0; o[nt][1] *= c0;
            o[nt][2] *= c1; o[nt][3] *= c1;
        }

        // ---- P -> fp16 A-fragments ----
        uint32_t pha[4][4];
#pragma unroll
        for (int js = 0; js < 4; js++) {
            const float* s0p = s[2*js];
            const float* s1p = s[2*js+1];
            pha[js][0] = pack_h2(s0p[0], s0p[1]);
            pha[js][1] = pack_h2(s0p[2], s0p[3]);
            pha[js][2] = pack_h2(s1p[0], s1p[1]);
            pha[js][3] = pack_h2(s1p[2], s1p[3]);
        }

        // ---- O += Ph Vh ----
#pragma unroll
        for (int js = 0; js < 4; js++) {
#pragma unroll
            for (int p = 0; p < 8; p++) {
                uint32_t vh[4];
                ldsm4t(vh, avh + js * (16 * VRS) + p * 32);
                mma16816(o[2*p],   pha[js], vh[0], vh[1]);
                mma16816(o[2*p+1], pha[js], vh[2], vh[3]);
            }
        }

        // ---- rotate pipeline ----
        __syncthreads();
        if (t + 2 < NTILES) {
            issue_group(sb, boff, t + 2, tid);
            CP_COMMIT();
            CP_WAIT(1);
        } else {
            CP_COMMIT();
            CP_WAIT(0);
        }
        __syncthreads();
    }

    // ---- epilogue ----
    l0 += __shfl_xor_sync(0xffffffffu, l0, 1);
    l0 += __shfl_xor_sync(0xffffffffu, l0, 2);
    l1 += __shfl_xor_sync(0xffffffffu, l1, 1);
    l1 += __shfl_xor_sync(0xffffffffu, l1, 2);
    float inv0 = 1.0f / l0, inv1 = 1.0f / l1;

    size_t row0 = (size_t)b * N_ + (size_t)qt * BM + m0 + (lane >> 2);
    float* p0 = O + row0 * D_;
    float* p1 = p0 + 8 * D_;
    int cbase = 2 * (lane & 3);
#pragma unroll
    for (int nt = 0; nt < 16; nt++) {
        int c = nt * 8 + cbase;
        *(float2*)(p0 + c) = make_float2(o[nt][0] * inv0, o[nt][1] * inv0);
        *(float2*)(p1 + c) = make_float2(o[nt][2] * inv1, o[nt][3] * inv1);
    }
}

// -------- launcher --------
extern "C" void kernel_launch(void* const* d_in, const int* in_sizes, int n_in,
                              void* d_out, int out_size) {
    const float* q = (const float*)d_in[0];
    const float* k = (const float*)d_in[1];
    const float* v = (const float*)d_in[2];
    float* o = (float*)d_out;

    prep_qk_kernel<<<(2 * B_ * N_ * 32) / NTP, NTP>>>(q, k);
    prep_v_kernel<<<(B_ * N_ * D_ / 2) / NTP, NTP>>>(v);

    cudaFuncSetAttribute(attn_imma_kernel, cudaFuncAttributeMaxDynamicSharedMemorySize, SMEM_TOTAL);
    attn_imma_kernel<<<dim3(N_ / BM, B_), NT, SMEM_TOTAL>>>(o);
}

// round 10
// speedup vs baseline: 3.0577x; 3.0577x over previous
#include <cuda_runtime.h>
#include <cuda_fp16.h>
#include <cstdint>

#define B_  16
#define N_  2048
#define D_  128
#define BM  128
#define BN  64
#define NT  256               // 8 warps
#define NTP 256
#define NTILES (N_/BN)        // 32
#define RS  272               // smem row stride (bytes)
#define TS  (64*RS)           // one 64x128 fp16 tile = 17408 B
#define SMEM_TOTAL (7*TS)     // K: 2 stages x (Kh,Kl); V: 3 stages -> 121856 B

// -------- static device scratch (fp16 hi/lo; Q pre-scaled by log2e) --------
__device__ __align__(256) __half g_Qh[B_*N_*D_];
__device__ __align__(256) __half g_Ql[B_*N_*D_];
__device__ __align__(256) __half g_Kh[B_*N_*D_];
__device__ __align__(256) __half g_Kl[B_*N_*D_];
__device__ __align__(256) __half g_Vh[B_*N_*D_];

// -------- PTX helpers (compute_103-safe) --------
__device__ __forceinline__ uint32_t smem_u32(const void* p) {
    uint32_t a;
    asm("{ .reg .u64 t; cvta.to.shared.u64 t, %1; cvt.u32.u64 %0, t; }" : "=r"(a) : "l"(p));
    return a;
}
__device__ __forceinline__ void cpa16(uint32_t dst, const void* src) {
    asm volatile("cp.async.cg.shared.global [%0], [%1], 16;" :: "r"(dst), "l"(src) : "memory");
}
#define CP_COMMIT() asm volatile("cp.async.commit_group;" ::: "memory")
#define CP_WAIT(n)  asm volatile("cp.async.wait_group %0;" :: "n"(n) : "memory")

__device__ __forceinline__ void ldsm4(uint32_t* r, uint32_t a) {
    asm volatile("ldmatrix.sync.aligned.m8n8.x4.shared.b16 {%0,%1,%2,%3}, [%4];"
        : "=r"(r[0]), "=r"(r[1]), "=r"(r[2]), "=r"(r[3]) : "r"(a));
}
__device__ __forceinline__ void ldsm4t(uint32_t* r, uint32_t a) {
    asm volatile("ldmatrix.sync.aligned.m8n8.x4.trans.shared.b16 {%0,%1,%2,%3}, [%4];"
        : "=r"(r[0]), "=r"(r[1]), "=r"(r[2]), "=r"(r[3]) : "r"(a));
}
__device__ __forceinline__ void mma16816(float* c, const uint32_t* a, uint32_t b0, uint32_t b1) {
    asm volatile(
        "mma.sync.aligned.m16n8k16.row.col.f32.f16.f16.f32 "
        "{%0,%1,%2,%3}, {%4,%5,%6,%7}, {%8,%9}, {%0,%1,%2,%3};"
        : "+f"(c[0]), "+f"(c[1]), "+f"(c[2]), "+f"(c[3])
        : "r"(a[0]), "r"(a[1]), "r"(a[2]), "r"(a[3]), "r"(b0), "r"(b1));
}
__device__ __forceinline__ uint32_t pack_h2(float a, float b) {
    __half2 h = __floats2half2_rn(a, b);
    return *(uint32_t*)&h;
}
__device__ __forceinline__ float ex2(float x) {
    float r;
    asm("ex2.approx.ftz.f32 %0, %1;" : "=f"(r) : "f"(x));
    return r;
}

// -------- prep --------
__global__ void prep_kernel(const float* __restrict__ Q, const float* __restrict__ K,
                            const float* __restrict__ V) {
    size_t i = (size_t)blockIdx.x * blockDim.x + threadIdx.x;
    float2 q = ((const float2*)Q)[i];
    q.x *= 1.44269504089f; q.y *= 1.44269504089f;
    __half2 qh = __floats2half2_rn(q.x, q.y);
    float2 qf = __half22float2(qh);
    ((__half2*)g_Qh)[i] = qh;
    ((__half2*)g_Ql)[i] = __floats2half2_rn(q.x - qf.x, q.y - qf.y);
    float2 k = ((const float2*)K)[i];
    __half2 kh = __floats2half2_rn(k.x, k.y);
    float2 kf = __half22float2(kh);
    ((__half2*)g_Kh)[i] = kh;
    ((__half2*)g_Kl)[i] = __floats2half2_rn(k.x - kf.x, k.y - kf.y);
    float2 v = ((const float2*)V)[i];
    ((__half2*)g_Vh)[i] = __floats2half2_rn(v.x, v.y);
}

// -------- smem loaders --------
__device__ __forceinline__ void cp_tile64(uint32_t dstbase, const __half* src, int tid) {
#pragma unroll
    for (int i = 0; i < 4; i++) {
        int g = tid + i * NT;
        int row = g >> 4, c = g & 15;
        cpa16(dstbase + row * RS + c * 16, (const char*)src + row * 256 + c * 16);
    }
}
__device__ __forceinline__ void cp_tile128(uint32_t dstbase, const __half* src, int tid) {
#pragma unroll
    for (int i = 0; i < 8; i++) {
        int g = tid + i * NT;
        int row = g >> 4, c = g & 15;
        cpa16(dstbase + row * RS + c * 16, (const char*)src + row * 256 + c * 16);
    }
}
// group u: Kh,Kl into K-stage u&1; Vh into V-stage u%3
__device__ __forceinline__ void issue_group(uint32_t sb, size_t kvbase, int u, int tid) {
    size_t off = kvbase + (size_t)u * BN * D_;
    uint32_t kb = sb + (uint32_t)(u & 1) * (2 * TS);
    cp_tile64(kb,      g_Kh + off, tid);
    cp_tile64(kb + TS, g_Kl + off, tid);
    cp_tile64(sb + 4 * TS + (uint32_t)(u % 3) * TS, g_Vh + off, tid);
}

// -------- main attention kernel: deferred-PV + software-pipelined fragments --------
__global__ void __launch_bounds__(NT, 1)
attn_mma_kernel(float* __restrict__ O)
{
    extern __shared__ __align__(1024) char smem[];
    uint32_t sb = smem_u32(smem);
    const int tid  = threadIdx.x;
    const int warp = tid >> 5;
    const int lane = tid & 31;
    const int qt = blockIdx.x;
    const int b  = blockIdx.y;

    const int m0 = warp * 16;
    const uint32_t qrow = m0 + (lane & 7) + ((lane & 8) ? 8 : 0);
    const uint32_t krow = (lane & 7) + ((lane & 16) ? 8 : 0);
    const uint32_t kcol = (lane & 8) ? 16 : 0;
    const uint32_t vrow = (lane & 7) + ((lane & 8) ? 8 : 0);
    const uint32_t vcol = (lane & 16) ? 16 : 0;

    // ---- stage Q through smem slots 0..3, hoist to registers, recycle ----
    const size_t qoff = ((size_t)b * N_ + (size_t)qt * BM) * D_;
    cp_tile128(sb,          g_Qh + qoff, tid);
    cp_tile128(sb + 2 * TS, g_Ql + qoff, tid);
    CP_COMMIT();
    CP_WAIT(0);
    __syncthreads();

    uint32_t qfh[8][4], qfl[8][4];
    {
        const uint32_t aq_h = sb + qrow * RS + ((lane & 16) ? 16 : 0);
        const uint32_t aq_l = aq_h + 2 * TS;
#pragma unroll
        for (int k = 0; k < 8; k++) {
            ldsm4(qfh[k], aq_h + k * 32);
            ldsm4(qfl[k], aq_l + k * 32);
        }
    }
    // zero V-stage 2 (read as "V(-1)" by the first, dummy PV)
    {
        uint32_t* vz = (uint32_t*)(smem + 6 * TS);
        for (int i = tid; i < TS / 4; i += NT) vz[i] = 0u;
    }
    __syncthreads();

    const size_t kvbase = (size_t)b * N_ * D_;
    issue_group(sb, kvbase, 0, tid);
    CP_COMMIT();

    float o[16][4];
#pragma unroll
    for (int i = 0; i < 16; i++)
#pragma unroll
        for (int j = 0; j < 4; j++) o[i][j] = 0.f;
    float m0r = -INFINITY, m1r = -INFINITY, l0 = 0.f, l1 = 0.f;
    uint32_t pha[4][4];
#pragma unroll
    for (int js = 0; js < 4; js++)
#pragma unroll
        for (int e = 0; e < 4; e++) pha[js][e] = 0u;

    for (int t = 0; t < NTILES; t++) {
        __syncthreads();                       // all warps done with stages being recycled
        if (t + 1 < NTILES) {
            issue_group(sb, kvbase, t + 1, tid);
            CP_COMMIT();
            CP_WAIT(1);                        // group t complete
        } else {
            CP_COMMIT();
            CP_WAIT(0);
        }
        __syncthreads();                       // cross-thread visibility of group t

        const uint32_t kb  = sb + (uint32_t)(t & 1) * (2 * TS);
        const uint32_t akh = kb + krow * RS + kcol;
        const uint32_t akl = akh + TS;
        const uint32_t avp = sb + 4 * TS + (uint32_t)((t + 2) % 3) * TS + vrow * RS + vcol; // V(t-1)

        // ---- S(t) = Q K^T, 3-term fp16 split; flattened + double-buffered ldsm ----
        float s[8][4];
#pragma unroll
        for (int i = 0; i < 8; i++)
#pragma unroll
            for (int j = 0; j < 4; j++) s[i][j] = 0.f;

        {
            uint32_t bufH[2][4], bufL[2][4];
            ldsm4(bufH[0], akh);
            ldsm4(bufL[0], akl);
#pragma unroll
            for (int i = 0; i < 32; i++) {
                if (i + 1 < 32) {
                    int kn = (i + 1) >> 2, pn = (i + 1) & 3;
                    ldsm4(bufH[(i + 1) & 1], akh + pn * (16 * RS) + kn * 32);
                    ldsm4(bufL[(i + 1) & 1], akl + pn * (16 * RS) + kn * 32);
                }
                const int k = i >> 2, p = i & 3;
                const uint32_t* bh = bufH[i & 1];
                const uint32_t* bl = bufL[i & 1];
                mma16816(s[2*p],   qfh[k], bh[0], bh[1]);
                mma16816(s[2*p+1], qfh[k], bh[2], bh[3]);
                mma16816(s[2*p],   qfl[k], bh[0], bh[1]);
                mma16816(s[2*p+1], qfl[k], bh[2], bh[3]);
                mma16816(s[2*p],   qfh[k], bl[0], bl[1]);
                mma16816(s[2*p+1], qfh[k], bl[2], bl[3]);
            }
        }

        // ---- softmax stats for tile t (MUFU-heavy; independent of PV below) ----
        float mx0 = s[0][0], mx1 = s[0][2];
#pragma unroll
        for (int nt = 0; nt < 8; nt++) {
            mx0 = fmaxf(mx0, fmaxf(s[nt][0], s[nt][1]));
            mx1 = fmaxf(mx1, fmaxf(s[nt][2], s[nt][3]));
        }
        mx0 = fmaxf(mx0, __shfl_xor_sync(0xffffffffu, mx0, 1));
        mx0 = fmaxf(mx0, __shfl_xor_sync(0xffffffffu, mx0, 2));
        mx1 = fmaxf(mx1, __shfl_xor_sync(0xffffffffu, mx1, 1));
        mx1 = fmaxf(mx1, __shfl_xor_sync(0xffffffffu, mx1, 2));
        float mn0 = fmaxf(m0r, mx0), mn1 = fmaxf(m1r, mx1);
        float c0 = ex2(m0r - mn0), c1 = ex2(m1r - mn1);
        m0r = mn0; m1r = mn1;
        float a0 = 0.f, a1 = 0.f;
#pragma unroll
        for (int nt = 0; nt < 8; nt++) {
            s[nt][0] = ex2(s[nt][0] - mn0); a0 += s[nt][0];
            s[nt][1] = ex2(s[nt][1] - mn0); a0 += s[nt][1];
            s[nt][2] = ex2(s[nt][2] - mn1); a1 += s[nt][2];
            s[nt][3] = ex2(s[nt][3] - mn1); a1 += s[nt][3];
        }
        l0 = l0 * c0 + a0;
        l1 = l1 * c1 + a1;

        // ---- PV(t-1): o += P(t-1) V(t-1); flattened + double-buffered ldsm ----
        {
            uint32_t bufV[2][4];
            ldsm4t(bufV[0], avp);
#pragma unroll
            for (int j = 0; j < 32; j++) {
                if (j + 1 < 32) {
                    int jn = (j + 1) >> 3, pn = (j + 1) & 7;
                    ldsm4t(bufV[(j + 1) & 1], avp + jn * (16 * RS) + pn * 32);
                }
                const int js = j >> 3, p = j & 7;
                const uint32_t* vh = bufV[j & 1];
                mma16816(o[2*p],   pha[js], vh[0], vh[1]);
                mma16816(o[2*p+1], pha[js], vh[2], vh[3]);
            }
        }

        // ---- rescale o into m(t) units (after PV adds) ----
#pragma unroll
        for (int nt = 0; nt < 16; nt++) {
            o[nt][0] *= c0; o[nt][1] *= c0;
            o[nt][2] *= c1; o[nt][3] *= c1;
        }

        // ---- pack P(t) for next iteration's PV ----
#pragma unroll
        for (int js = 0; js < 4; js++) {
            const float* s0p = s[2*js];
            const float* s1p = s[2*js+1];
            pha[js][0] = pack_h2(s0p[0], s0p[1]);
            pha[js][1] = pack_h2(s0p[2], s0p[3]);
            pha[js][2] = pack_h2(s1p[0], s1p[1]);
            pha[js][3] = pack_h2(s1p[2], s1p[3]);
        }
    }

    // ---- final PV(NTILES-1) ----
    {
        const uint32_t avp = sb + 4 * TS + (uint32_t)((NTILES - 1) % 3) * TS + vrow * RS + vcol;
#pragma unroll
        for (int js = 0; js < 4; js++) {
#pragma unroll
            for (int p = 0; p < 8; p++) {
                uint32_t vh[4];
                ldsm4t(vh, avp + js * (16 * RS) + p * 32);
                mma16816(o[2*p],   pha[js], vh[0], vh[1]);
                mma16816(o[2*p+1], pha[js], vh[2], vh[3]);
            }
        }
    }

    // ---- epilogue ----
    l0 += __shfl_xor_sync(0xffffffffu, l0, 1);
    l0 += __shfl_xor_sync(0xffffffffu, l0, 2);
    l1 += __shfl_xor_sync(0xffffffffu, l1, 1);
    l1 += __shfl_xor_sync(0xffffffffu, l1, 2);
    float inv0 = 1.0f / l0, inv1 = 1.0f / l1;

    size_t row0 = (size_t)b * N_ + (size_t)qt * BM + m0 + (lane >> 2);
    float* p0 = O + row0 * D_;
    float* p1 = p0 + 8 * D_;
    int cbase = 2 * (lane & 3);
#pragma unroll
    for (int nt = 0; nt < 16; nt++) {
        int c = nt * 8 + cbase;
        *(float2*)(p0 + c) = make_float2(o[nt][0] * inv0, o[nt][1] * inv0);
        *(float2*)(p1 + c) = make_float2(o[nt][2] * inv1, o[nt][3] * inv1);
    }
}

// -------- launcher --------
extern "C" void kernel_launch(void* const* d_in, const int* in_sizes, int n_in,
                              void* d_out, int out_size) {
    const float* q = (const float*)d_in[0];
    const float* k = (const float*)d_in[1];
    const float* v = (const float*)d_in[2];
    float* o = (float*)d_out;

    prep_kernel<<<(B_ * N_ * D_ / 2) / NTP, NTP>>>(q, k, v);

    cudaFuncSetAttribute(attn_mma_kernel, cudaFuncAttributeMaxDynamicSharedMemorySize, SMEM_TOTAL);
    attn_mma_kernel<<<dim3(N_ / BM, B_), NT, SMEM_TOTAL>>>(o);
}